// round 4
// baseline (speedup 1.0000x reference)
#include <cuda_runtime.h>

// Problem constants
#define T_  4
#define B_  16
#define C_  512
#define N_  1024
#define CR_ 64
#define TB_ (T_ * B_)          // 64
#define BN_EPS 1e-5f

// Scratch (allocation-free rule: __device__ globals)
__device__ float g_gap[TB_ * C_];   // [64, 512]
__device__ float g_h1[TB_ * CR_];   // [64, 64]

// ---------------------------------------------------------------------------
// K1: LIF over T=4 + GAP over N, fused. One block per (b, c).
// 256 threads, each owns 4 consecutive n (one float4 covers N=1024 exactly).
// Loads for all 4 timesteps issued up front (independent addresses, MLP=4),
// streaming hint (__ldcs) since x is touched exactly once.
// ---------------------------------------------------------------------------
__global__ void __launch_bounds__(256) lif_gap_kernel(const float* __restrict__ x,
                                                      float* __restrict__ g) {
    const int bc  = blockIdx.x;          // 0..8191
    const int b   = bc >> 9;             // /512
    const int c   = bc & (C_ - 1);
    const int tid = threadIdx.x;

    const size_t strideT = (size_t)B_ * C_ * N_;     // elements per timestep
    const size_t base = ((size_t)b * C_ + c) * N_ + (size_t)tid * 4;

    // Front-batched loads: 4 independent float4s (streaming)
    float4 xt[T_];
#pragma unroll
    for (int t = 0; t < T_; t++) {
        xt[t] = __ldcs(reinterpret_cast<const float4*>(x + base + (size_t)t * strideT));
    }

    // LIF per n-slot; accumulate spike count per timestep
    float sums[T_] = {0.f, 0.f, 0.f, 0.f};
#pragma unroll
    for (int slot = 0; slot < 4; slot++) {
        float v = 0.f;
#pragma unroll
        for (int t = 0; t < T_; t++) {
            float xv = (slot == 0) ? xt[t].x : (slot == 1) ? xt[t].y
                     : (slot == 2) ? xt[t].z : xt[t].w;
            v = 0.5f * (v + xv);                 // v += (x - v)/TAU, TAU=2
            float s = (v >= 1.0f) ? 1.0f : 0.0f; // spike(v - V_TH)
            sums[t] += s;
            v *= (1.0f - s);                     // hard reset (detached)
        }
    }

    // Block reduction of sums[4] over 256 threads (8 warps)
    __shared__ float red[8][T_];
    const int lane = tid & 31;
    const int wid  = tid >> 5;
#pragma unroll
    for (int t = 0; t < T_; t++) {
#pragma unroll
        for (int off = 16; off > 0; off >>= 1)
            sums[t] += __shfl_xor_sync(0xFFFFFFFFu, sums[t], off);
    }
    if (lane == 0) {
#pragma unroll
        for (int t = 0; t < T_; t++) red[wid][t] = sums[t];
    }
    __syncthreads();

    // Lanes 0..3 of warp 0 finalize one timestep each
    if (tid < T_) {
        float tot = 0.f;
#pragma unroll
        for (int w = 0; w < 8; w++) tot += red[w][tid];
        // g[(t*B + b) * C + c] = mean over N
        g[((tid * B_ + b) * C_) + c] = tot * (1.0f / (float)N_);
    }
}

// ---------------------------------------------------------------------------
// K2: h1 = BN1(g @ w1^T + b1). One block per output column j (Cr=64 blocks),
// 64 threads = one per row i. BN column stats reduce inside the block.
// ---------------------------------------------------------------------------
__global__ void __launch_bounds__(64) fc1_bn_kernel(const float* __restrict__ g,
                                                    const float* __restrict__ w1,
                                                    const float* __restrict__ b1,
                                                    const float* __restrict__ gamma1,
                                                    const float* __restrict__ beta1,
                                                    float* __restrict__ h1) {
    const int j = blockIdx.x;   // 0..63  output channel
    const int i = threadIdx.x;  // 0..63  batch row

    const float4* gr = reinterpret_cast<const float4*>(g + (size_t)i * C_);
    const float4* wr = reinterpret_cast<const float4*>(w1 + (size_t)j * C_);
    float acc = 0.f;
#pragma unroll 8
    for (int k = 0; k < C_ / 4; k++) {
        float4 a = gr[k], w = wr[k];
        acc += a.x * w.x + a.y * w.y + a.z * w.z + a.w * w.w;
    }
    float h = acc + b1[j];

    // Column stats over 64 rows (2 warps)
    float s = h, q = h * h;
#pragma unroll
    for (int off = 16; off > 0; off >>= 1) {
        s += __shfl_xor_sync(0xFFFFFFFFu, s, off);
        q += __shfl_xor_sync(0xFFFFFFFFu, q, off);
    }
    __shared__ float ss[2], sq[2];
    if ((i & 31) == 0) { ss[i >> 5] = s; sq[i >> 5] = q; }
    __syncthreads();
    float mu  = (ss[0] + ss[1]) * (1.0f / (float)TB_);
    float ex2 = (sq[0] + sq[1]) * (1.0f / (float)TB_);
    float var = ex2 - mu * mu;

    h1[i * CR_ + j] = (h - mu) * rsqrtf(var + BN_EPS) * gamma1[j] + beta1[j];
}

// ---------------------------------------------------------------------------
// K3: out = BN2(h1 @ w2^T + b2). One block per output column j (C=512 blocks),
// 64 threads = one per row i. Writes d_out[i*512 + j] directly.
// ---------------------------------------------------------------------------
__global__ void __launch_bounds__(64) fc2_bn_kernel(const float* __restrict__ h1,
                                                    const float* __restrict__ w2,
                                                    const float* __restrict__ b2,
                                                    const float* __restrict__ gamma2,
                                                    const float* __restrict__ beta2,
                                                    float* __restrict__ out) {
    const int j = blockIdx.x;   // 0..511 output channel
    const int i = threadIdx.x;  // 0..63  batch row

    const float4* hr = reinterpret_cast<const float4*>(h1 + (size_t)i * CR_);
    const float4* wr = reinterpret_cast<const float4*>(w2 + (size_t)j * CR_);
    float acc = 0.f;
#pragma unroll
    for (int k = 0; k < CR_ / 4; k++) {
        float4 a = hr[k], w = wr[k];
        acc += a.x * w.x + a.y * w.y + a.z * w.z + a.w * w.w;
    }
    float h = acc + b2[j];

    float s = h, q = h * h;
#pragma unroll
    for (int off = 16; off > 0; off >>= 1) {
        s += __shfl_xor_sync(0xFFFFFFFFu, s, off);
        q += __shfl_xor_sync(0xFFFFFFFFu, q, off);
    }
    __shared__ float ss[2], sq[2];
    if ((i & 31) == 0) { ss[i >> 5] = s; sq[i >> 5] = q; }
    __syncthreads();
    float mu  = (ss[0] + ss[1]) * (1.0f / (float)TB_);
    float ex2 = (sq[0] + sq[1]) * (1.0f / (float)TB_);
    float var = ex2 - mu * mu;

    out[i * C_ + j] = (h - mu) * rsqrtf(var + BN_EPS) * gamma2[j] + beta2[j];
}

// ---------------------------------------------------------------------------
extern "C" void kernel_launch(void* const* d_in, const int* in_sizes, int n_in,
                              void* d_out, int out_size) {
    const float* x      = (const float*)d_in[0];
    const float* w1     = (const float*)d_in[1];
    const float* b1     = (const float*)d_in[2];
    const float* gamma1 = (const float*)d_in[3];
    const float* beta1  = (const float*)d_in[4];
    const float* w2     = (const float*)d_in[5];
    const float* b2     = (const float*)d_in[6];
    const float* gamma2 = (const float*)d_in[7];
    const float* beta2  = (const float*)d_in[8];
    float* out = (float*)d_out;

    float* g;  cudaGetSymbolAddress((void**)&g,  g_gap);
    float* h1; cudaGetSymbolAddress((void**)&h1, g_h1);

    lif_gap_kernel<<<B_ * C_, 256>>>(x, g);
    fc1_bn_kernel<<<CR_, 64>>>(g, w1, b1, gamma1, beta1, h1);
    fc2_bn_kernel<<<C_, 64>>>(h1, w2, b2, gamma2, beta2, out);
}

// round 6
// speedup vs baseline: 1.2199x; 1.2199x over previous
#include <cuda_runtime.h>

// Problem constants
#define T_  4
#define B_  16
#define C_  512
#define N_  1024
#define CR_ 64
#define TB_ (T_ * B_)          // 64
#define BN_EPS 1e-5f

// Scratch (allocation-free rule: __device__ globals)
__device__ float g_gap[TB_ * C_];   // [64, 512]
__device__ float g_h1[TB_ * CR_];   // [64, 64]

// ---------------------------------------------------------------------------
// K1: LIF over T=4 + GAP over N. One block per (b, channel-pair): 4096 blocks.
// Each thread front-batches 8 independent float4 loads (2 channels x 4 steps)
// -> MLP_p1 = 8. Streaming (__ldcs): x touched exactly once.
// Blocks 0..7 additionally prefetch w1/w2 into L2 for the downstream kernels.
// ---------------------------------------------------------------------------
__global__ void __launch_bounds__(256) lif_gap_kernel(const float* __restrict__ x,
                                                      const float* __restrict__ w1,
                                                      const float* __restrict__ w2,
                                                      float* __restrict__ g) {
    const int p     = blockIdx.x;        // 0..4095
    const int b     = p >> 8;            // /256 pairs per batch
    const int cpair = p & 255;
    const int c0    = cpair << 1;
    const int tid   = threadIdx.x;

    // L2 warm-up for the MLP weights (128 KB each, 1024 lines of 128 B)
    if (p < 8) {
        const float* wsrc = (p < 4) ? w1 : w2;
        const char* line = (const char*)wsrc + ((size_t)(p & 3) * 256 + tid) * 128;
        asm volatile("prefetch.global.L2 [%0];" :: "l"(line));
    }

    const size_t strideT = (size_t)B_ * C_ * N_;
    const size_t base0 = ((size_t)b * C_ + c0) * N_ + (size_t)tid * 4;

    // Front-batched: 8 independent float4 loads
    float4 xt[2][T_];
#pragma unroll
    for (int ch = 0; ch < 2; ch++)
#pragma unroll
        for (int t = 0; t < T_; t++)
            xt[ch][t] = __ldcs(reinterpret_cast<const float4*>(
                x + base0 + (size_t)ch * N_ + (size_t)t * strideT));

    // LIF recurrence per n-slot; spike counts per (channel, timestep)
    float sums[8] = {0.f,0.f,0.f,0.f,0.f,0.f,0.f,0.f};
#pragma unroll
    for (int ch = 0; ch < 2; ch++) {
#pragma unroll
        for (int slot = 0; slot < 4; slot++) {
            float v = 0.f;
#pragma unroll
            for (int t = 0; t < T_; t++) {
                float4 q = xt[ch][t];
                float xv = (slot == 0) ? q.x : (slot == 1) ? q.y
                         : (slot == 2) ? q.z : q.w;
                v = 0.5f * (v + xv);                 // v += (x - v)/TAU, TAU=2
                float s = (v >= 1.0f) ? 1.0f : 0.0f; // spike(v - V_TH)
                sums[ch * 4 + t] += s;
                v *= (1.0f - s);                     // hard reset
            }
        }
    }

    // Block reduction of 8 partials over 256 threads (8 warps)
    __shared__ float red[8][8];
    const int lane = tid & 31;
    const int wid  = tid >> 5;
#pragma unroll
    for (int v = 0; v < 8; v++) {
#pragma unroll
        for (int off = 16; off > 0; off >>= 1)
            sums[v] += __shfl_xor_sync(0xFFFFFFFFu, sums[v], off);
    }
    if (lane == 0) {
#pragma unroll
        for (int v = 0; v < 8; v++) red[wid][v] = sums[v];
    }
    __syncthreads();

    if (tid < 8) {
        float tot = 0.f;
#pragma unroll
        for (int w = 0; w < 8; w++) tot += red[w][tid];
        const int ch = tid >> 2, t = tid & 3;
        g[((t * B_ + b) * C_) + (c0 + ch)] = tot * (1.0f / (float)N_);
    }
}

// ---------------------------------------------------------------------------
// K2: h1 = BN1(g @ w1^T + b1). One block per output column j (64 blocks),
// 256 threads. w1 row staged in smem; warp-per-row coalesced g reads;
// warp-shuffle dot reduction; BN column stats in-block.
// ---------------------------------------------------------------------------
__global__ void __launch_bounds__(256) fc1_bn_kernel(const float* __restrict__ g,
                                                     const float* __restrict__ w1,
                                                     const float* __restrict__ b1,
                                                     const float* __restrict__ gamma1,
                                                     const float* __restrict__ beta1,
                                                     float* __restrict__ h1) {
    const int j   = blockIdx.x;   // output channel
    const int tid = threadIdx.x;
    __shared__ float4 w1s[C_ / 4];     // 2 KB
    __shared__ float  hrow[TB_];
    __shared__ float  ss[2], sq[2];

    if (tid < C_ / 4)
        w1s[tid] = reinterpret_cast<const float4*>(w1 + (size_t)j * C_)[tid];
    __syncthreads();

    const int w = tid >> 5, l = tid & 31;
#pragma unroll
    for (int r = 0; r < 8; r++) {
        const int i = w * 8 + r;                       // batch row 0..63
        const float4* gr = reinterpret_cast<const float4*>(g + (size_t)i * C_);
        float acc = 0.f;
#pragma unroll
        for (int s = 0; s < 4; s++) {                  // 32-lane coalesced
            float4 a = gr[l + s * 32], wv = w1s[l + s * 32];
            acc += a.x * wv.x + a.y * wv.y + a.z * wv.z + a.w * wv.w;
        }
#pragma unroll
        for (int off = 16; off > 0; off >>= 1)
            acc += __shfl_xor_sync(0xFFFFFFFFu, acc, off);
        if (l == 0) hrow[i] = acc + b1[j];
    }
    __syncthreads();

    if (tid < TB_) {
        float h = hrow[tid];
        float s = h, q = h * h;
#pragma unroll
        for (int off = 16; off > 0; off >>= 1) {
            s += __shfl_xor_sync(0xFFFFFFFFu, s, off);
            q += __shfl_xor_sync(0xFFFFFFFFu, q, off);
        }
        if ((tid & 31) == 0) { ss[tid >> 5] = s; sq[tid >> 5] = q; }
    }
    __syncthreads();
    if (tid < TB_) {
        float mu  = (ss[0] + sq[0] * 0.f + ss[1]) * (1.0f / (float)TB_);
        float ex2 = (sq[0] + sq[1]) * (1.0f / (float)TB_);
        float var = ex2 - mu * mu;
        h1[tid * CR_ + j] = (hrow[tid] - mu) * rsqrtf(var + BN_EPS) * gamma1[j] + beta1[j];
    }
}

// ---------------------------------------------------------------------------
// K3: out = BN2(h1 @ w2^T + b2). One block per output column j (512 blocks),
// 64 threads = one per row. w2 row is a lane-uniform broadcast; h1 (16 KB)
// is L1/L2 resident. 4 accumulators break the FMA dependency chain.
// ---------------------------------------------------------------------------
__global__ void __launch_bounds__(64) fc2_bn_kernel(const float* __restrict__ h1,
                                                    const float* __restrict__ w2,
                                                    const float* __restrict__ b2,
                                                    const float* __restrict__ gamma2,
                                                    const float* __restrict__ beta2,
                                                    float* __restrict__ out) {
    const int j = blockIdx.x;   // 0..511
    const int i = threadIdx.x;  // 0..63

    const float4* hr = reinterpret_cast<const float4*>(h1 + (size_t)i * CR_);
    const float4* wr = reinterpret_cast<const float4*>(w2 + (size_t)j * CR_);
    float a0 = 0.f, a1 = 0.f, a2 = 0.f, a3 = 0.f;
#pragma unroll
    for (int k = 0; k < CR_ / 16; k++) {
        float4 x0 = hr[k * 4 + 0], w0 = wr[k * 4 + 0];
        float4 x1 = hr[k * 4 + 1], w1v = wr[k * 4 + 1];
        float4 x2 = hr[k * 4 + 2], w2v = wr[k * 4 + 2];
        float4 x3 = hr[k * 4 + 3], w3 = wr[k * 4 + 3];
        a0 += x0.x * w0.x + x0.y * w0.y + x0.z * w0.z + x0.w * w0.w;
        a1 += x1.x * w1v.x + x1.y * w1v.y + x1.z * w1v.z + x1.w * w1v.w;
        a2 += x2.x * w2v.x + x2.y * w2v.y + x2.z * w2v.z + x2.w * w2v.w;
        a3 += x3.x * w3.x + x3.y * w3.y + x3.z * w3.z + x3.w * w3.w;
    }
    float h = (a0 + a1) + (a2 + a3) + b2[j];

    float s = h, q = h * h;
#pragma unroll
    for (int off = 16; off > 0; off >>= 1) {
        s += __shfl_xor_sync(0xFFFFFFFFu, s, off);
        q += __shfl_xor_sync(0xFFFFFFFFu, q, off);
    }
    __shared__ float ss[2], sq[2];
    if ((i & 31) == 0) { ss[i >> 5] = s; sq[i >> 5] = q; }
    __syncthreads();
    float mu  = (ss[0] + ss[1]) * (1.0f / (float)TB_);
    float ex2 = (sq[0] + sq[1]) * (1.0f / (float)TB_);
    float var = ex2 - mu * mu;

    out[i * C_ + j] = (h - mu) * rsqrtf(var + BN_EPS) * gamma2[j] + beta2[j];
}

// ---------------------------------------------------------------------------
extern "C" void kernel_launch(void* const* d_in, const int* in_sizes, int n_in,
                              void* d_out, int out_size) {
    const float* x      = (const float*)d_in[0];
    const float* w1     = (const float*)d_in[1];
    const float* b1     = (const float*)d_in[2];
    const float* gamma1 = (const float*)d_in[3];
    const float* beta1  = (const float*)d_in[4];
    const float* w2     = (const float*)d_in[5];
    const float* b2     = (const float*)d_in[6];
    const float* gamma2 = (const float*)d_in[7];
    const float* beta2  = (const float*)d_in[8];
    float* out = (float*)d_out;

    float* g;  cudaGetSymbolAddress((void**)&g,  g_gap);
    float* h1; cudaGetSymbolAddress((void**)&h1, g_h1);

    lif_gap_kernel<<<B_ * C_ / 2, 256>>>(x, w1, w2, g);
    fc1_bn_kernel<<<CR_, 256>>>(g, w1, b1, gamma1, beta1, h1);
    fc2_bn_kernel<<<C_, 64>>>(h1, w2, b2, gamma2, beta2, out);
}

// round 8
// speedup vs baseline: 1.3509x; 1.1074x over previous
#include <cuda_runtime.h>

// Problem constants
#define T_  4
#define B_  16
#define C_  512
#define N_  1024
#define CR_ 64
#define TB_ (T_ * B_)          // 64
#define BN_EPS 1e-5f

// Scratch (allocation-free rule: __device__ globals)
__device__ float g_gap[TB_ * C_];   // [64, 512]
__device__ float g_h1[TB_ * CR_];   // [64, 64]

// Software grid barrier state (generation counter survives graph replays:
// count always returns to 0, gen monotonically increases -> deterministic).
__device__ unsigned g_bar_count = 0;
__device__ volatile unsigned g_bar_gen = 0;

// ---------------------------------------------------------------------------
// K1: LIF over T=4 + GAP over N, fused. One block per (b, c): 8192 blocks.
// 256 threads, each owns one float4 per timestep (MLP_p1 = 4, front-batched).
// Streaming loads (__ldcs): x is touched exactly once.
// Blocks 0..7 prefetch w1/w2 into L2 for the MLP kernel (free under DRAM-bound K1).
// ---------------------------------------------------------------------------
__global__ void __launch_bounds__(256) lif_gap_kernel(const float* __restrict__ x,
                                                      const float* __restrict__ w1,
                                                      const float* __restrict__ w2,
                                                      float* __restrict__ g) {
    const int bc  = blockIdx.x;          // 0..8191
    const int b   = bc >> 9;             // /512
    const int c   = bc & (C_ - 1);
    const int tid = threadIdx.x;

    // L2 warm-up for MLP weights (128 KB each = 1024 lines of 128 B)
    if (bc < 8) {
        const float* wsrc = (bc < 4) ? w1 : w2;
        const char* line = (const char*)wsrc + ((size_t)(bc & 3) * 256 + tid) * 128;
        asm volatile("prefetch.global.L2 [%0];" :: "l"(line));
    }

    const size_t strideT = (size_t)B_ * C_ * N_;     // elements per timestep
    const size_t base = ((size_t)b * C_ + c) * N_ + (size_t)tid * 4;

    // Front-batched loads: 4 independent float4s
    float4 xt[T_];
#pragma unroll
    for (int t = 0; t < T_; t++)
        xt[t] = __ldcs(reinterpret_cast<const float4*>(x + base + (size_t)t * strideT));

    // LIF per n-slot; accumulate spike count per timestep
    float sums[T_] = {0.f, 0.f, 0.f, 0.f};
#pragma unroll
    for (int slot = 0; slot < 4; slot++) {
        float v = 0.f;
#pragma unroll
        for (int t = 0; t < T_; t++) {
            float xv = (slot == 0) ? xt[t].x : (slot == 1) ? xt[t].y
                     : (slot == 2) ? xt[t].z : xt[t].w;
            v = 0.5f * (v + xv);                 // v += (x - v)/TAU, TAU=2
            float s = (v >= 1.0f) ? 1.0f : 0.0f; // spike(v - V_TH)
            sums[t] += s;
            v *= (1.0f - s);                     // hard reset (detached)
        }
    }

    // Block reduction over 256 threads (8 warps)
    __shared__ float red[8][T_];
    const int lane = tid & 31;
    const int wid  = tid >> 5;
#pragma unroll
    for (int t = 0; t < T_; t++) {
#pragma unroll
        for (int off = 16; off > 0; off >>= 1)
            sums[t] += __shfl_xor_sync(0xFFFFFFFFu, sums[t], off);
    }
    if (lane == 0) {
#pragma unroll
        for (int t = 0; t < T_; t++) red[wid][t] = sums[t];
    }
    __syncthreads();

    if (tid < T_) {
        float tot = 0.f;
#pragma unroll
        for (int w = 0; w < 8; w++) tot += red[w][tid];
        g[((tid * B_ + b) * C_) + c] = tot * (1.0f / (float)N_);
    }
}

// ---------------------------------------------------------------------------
// K2: full MLP, fused. 64 blocks x 256 threads, all co-resident.
// Phase 1 (block = output column j of FC1): w1 row in smem, warp-per-row
// coalesced g reads, fused BN1, write h1 column j.
// Software grid barrier.
// Phase 2 (block handles 8 FC2 output columns): 4 parallel 64-thread groups,
// fused BN2, write d_out.
// ---------------------------------------------------------------------------
__global__ void __launch_bounds__(256) mlp_fused_kernel(const float* __restrict__ g,
                                                        const float* __restrict__ w1,
                                                        const float* __restrict__ b1,
                                                        const float* __restrict__ gamma1,
                                                        const float* __restrict__ beta1,
                                                        const float* __restrict__ w2,
                                                        const float* __restrict__ b2,
                                                        const float* __restrict__ gamma2,
                                                        const float* __restrict__ beta2,
                                                        float* __restrict__ h1,
                                                        float* __restrict__ out) {
    const int j   = blockIdx.x;   // 0..63
    const int tid = threadIdx.x;

    // ---------------- Phase 1: h1[:, j] = BN1(g @ w1[j,:] + b1[j]) ----------
    __shared__ float4 w1s[C_ / 4];     // 2 KB
    __shared__ float  hrow[TB_];
    __shared__ float  ss[4][2], sq[4][2];

    if (tid < C_ / 4)
        w1s[tid] = reinterpret_cast<const float4*>(w1 + (size_t)j * C_)[tid];
    __syncthreads();

    const int w = tid >> 5, l = tid & 31;
#pragma unroll
    for (int r = 0; r < 8; r++) {
        const int i = w * 8 + r;                       // batch row 0..63
        const float4* gr = reinterpret_cast<const float4*>(g + (size_t)i * C_);
        float acc = 0.f;
#pragma unroll
        for (int s = 0; s < 4; s++) {                  // 32-lane coalesced
            float4 a = gr[l + s * 32], wv = w1s[l + s * 32];
            acc += a.x * wv.x + a.y * wv.y + a.z * wv.z + a.w * wv.w;
        }
#pragma unroll
        for (int off = 16; off > 0; off >>= 1)
            acc += __shfl_xor_sync(0xFFFFFFFFu, acc, off);
        if (l == 0) hrow[i] = acc + b1[j];
    }
    __syncthreads();

    if (tid < TB_) {
        float h = hrow[tid];
        float s = h, q = h * h;
#pragma unroll
        for (int off = 16; off > 0; off >>= 1) {
            s += __shfl_xor_sync(0xFFFFFFFFu, s, off);
            q += __shfl_xor_sync(0xFFFFFFFFu, q, off);
        }
        if ((tid & 31) == 0) { ss[0][tid >> 5] = s; sq[0][tid >> 5] = q; }
    }
    __syncthreads();
    if (tid < TB_) {
        float mu  = (ss[0][0] + ss[0][1]) * (1.0f / (float)TB_);
        float ex2 = (sq[0][0] + sq[0][1]) * (1.0f / (float)TB_);
        float var = ex2 - mu * mu;
        h1[tid * CR_ + j] = (hrow[tid] - mu) * rsqrtf(var + BN_EPS) * gamma1[j] + beta1[j];
    }
    __syncthreads();

    // ---------------- Grid barrier (all 64 blocks co-resident) --------------
    if (tid == 0) {
        __threadfence();                               // publish h1
        unsigned gen = g_bar_gen;
        unsigned old = atomicAdd(&g_bar_count, 1);
        if (old == (unsigned)(gridDim.x - 1)) {
            g_bar_count = 0;
            __threadfence();
            g_bar_gen = gen + 1;                       // release
        } else {
            while (g_bar_gen == gen) __nanosleep(40);  // HW-sleep poll
        }
    }
    __syncthreads();
    __threadfence();                                   // acquire h1

    // ---------------- Phase 2: out[:, j*8 .. j*8+7] -------------------------
    const int grp = tid >> 6;     // 0..3 (column group)
    const int gt  = tid & 63;     // batch row i
    const int gw  = (tid >> 5) & 1; // warp-within-group

#pragma unroll
    for (int rep = 0; rep < 2; rep++) {
        const int jj = j * 8 + rep * 4 + grp;          // FC2 output column
        const float4* hr = reinterpret_cast<const float4*>(h1 + (size_t)gt * CR_);
        const float4* wr = reinterpret_cast<const float4*>(w2 + (size_t)jj * CR_);
        float a0 = 0.f, a1 = 0.f, a2 = 0.f, a3 = 0.f;
#pragma unroll
        for (int k = 0; k < CR_ / 16; k++) {
            float4 x0 = hr[k * 4 + 0], w0 = wr[k * 4 + 0];
            float4 x1 = hr[k * 4 + 1], w1v = wr[k * 4 + 1];
            float4 x2 = hr[k * 4 + 2], w2v = wr[k * 4 + 2];
            float4 x3 = hr[k * 4 + 3], w3 = wr[k * 4 + 3];
            a0 += x0.x * w0.x + x0.y * w0.y + x0.z * w0.z + x0.w * w0.w;
            a1 += x1.x * w1v.x + x1.y * w1v.y + x1.z * w1v.z + x1.w * w1v.w;
            a2 += x2.x * w2v.x + x2.y * w2v.y + x2.z * w2v.z + x2.w * w2v.w;
            a3 += x3.x * w3.x + x3.y * w3.y + x3.z * w3.z + x3.w * w3.w;
        }
        float h = (a0 + a1) + (a2 + a3) + b2[jj];

        float s = h, q = h * h;
#pragma unroll
        for (int off = 16; off > 0; off >>= 1) {
            s += __shfl_xor_sync(0xFFFFFFFFu, s, off);
            q += __shfl_xor_sync(0xFFFFFFFFu, q, off);
        }
        if ((gt & 31) == 0) { ss[grp][gw] = s; sq[grp][gw] = q; }
        __syncthreads();
        float mu  = (ss[grp][0] + ss[grp][1]) * (1.0f / (float)TB_);
        float ex2 = (sq[grp][0] + sq[grp][1]) * (1.0f / (float)TB_);
        float var = ex2 - mu * mu;
        out[gt * C_ + jj] = (h - mu) * rsqrtf(var + BN_EPS) * gamma2[jj] + beta2[jj];
        __syncthreads();
    }
}

// ---------------------------------------------------------------------------
extern "C" void kernel_launch(void* const* d_in, const int* in_sizes, int n_in,
                              void* d_out, int out_size) {
    const float* x      = (const float*)d_in[0];
    const float* w1     = (const float*)d_in[1];
    const float* b1     = (const float*)d_in[2];
    const float* gamma1 = (const float*)d_in[3];
    const float* beta1  = (const float*)d_in[4];
    const float* w2     = (const float*)d_in[5];
    const float* b2     = (const float*)d_in[6];
    const float* gamma2 = (const float*)d_in[7];
    const float* beta2  = (const float*)d_in[8];
    float* out = (float*)d_out;

    float* g;  cudaGetSymbolAddress((void**)&g,  g_gap);
    float* h1; cudaGetSymbolAddress((void**)&h1, g_h1);

    lif_gap_kernel<<<B_ * C_, 256>>>(x, w1, w2, g);
    mlp_fused_kernel<<<CR_, 256>>>(g, w1, b1, gamma1, beta1,
                                   w2, b2, gamma2, beta2, h1, out);
}